// round 1
// baseline (speedup 1.0000x reference)
#include <cuda_runtime.h>
#include <cuda_bf16.h>

// Per-channel class frequencies (compile-time constants from the reference).
__constant__ float c_W[23] = {
    0.0012597430655963838f, 0.0004919313290455535f, 0.0021106513104319356f,
    0.0007678117365508301f, 0.004719881670572202f,  0.000372272357115554f,
    0.029090425620315438f,  0.010056339432617042f,  0.0034817436971298467f,
    0.0003057951504877765f, 0.003995280118329428f,  8.808229878180519e-05f,
    0.012070598793438699f,  0.016788818533845208f,  0.0017832510677901316f,
    0.0008758371973209686f, 0.0005933090691529143f, 0.0031992155689617922f,
    0.003212511010287348f,  0.0016685778863572154f, 0.0009356666832859684f,
    0.0010985358395240233f, 0.00103372056306194f
};

// Global scratch accumulator (no allocations allowed).
__device__ double g_acc;

__global__ void bce_zero_kernel() {
    g_acc = 0.0;
}

__global__ void bce_main_kernel(const float4* __restrict__ x4,
                                const int4*   __restrict__ l4,
                                long long n_vec, int rem,
                                const float* __restrict__ x_tail,
                                const int*   __restrict__ l_tail,
                                long long tail_base) {
    __shared__ float s_w0[23];  // weight applied when label == 0  (= W+1)
    __shared__ float s_w1[23];  // weight applied when label == 1  (= 1 + 1/W)
    __shared__ float s_part[32];

    const int t = threadIdx.x;
    if (t < 23) {
        float w = c_W[t];
        s_w0[t] = w + 1.0f;
        s_w1[t] = 1.0f + __frcp_rn(w);
    }
    __syncthreads();

    float acc = 0.0f;
    const long long stride = (long long)gridDim.x * blockDim.x;
    long long gtid = (long long)blockIdx.x * blockDim.x + t;

    for (long long v = gtid; v < n_vec; v += stride) {
        float4 xv = __ldg(&x4[v]);
        int4   lv = __ldg(&l4[v]);
        int c = (int)((4ll * v) % 23);

        float xs[4] = { xv.x, xv.y, xv.z, xv.w };
        int   ls[4] = { lv.x, lv.y, lv.z, lv.w };
        #pragma unroll
        for (int j = 0; j < 4; ++j) {
            bool  pos = (ls[j] > 0);
            float arg = pos ? xs[j] : (1.0f - xs[j]);
            float w   = pos ? s_w1[c] : s_w0[c];
            // loss term = w * (-log(arg))
            acc = fmaf(w, -__logf(arg), acc);
            c = (c == 22) ? 0 : (c + 1);
        }
    }

    // scalar tail (n % 4 elements), handled by the first `rem` global threads
    if (gtid < rem) {
        long long i = tail_base + gtid;
        int   lab = __ldg(&l_tail[gtid]);
        float xv  = __ldg(&x_tail[gtid]);
        int   c   = (int)(i % 23);
        bool  pos = (lab > 0);
        float arg = pos ? xv : (1.0f - xv);
        float w   = pos ? s_w1[c] : s_w0[c];
        acc = fmaf(w, -__logf(arg), acc);
    }

    // warp reduce
    #pragma unroll
    for (int o = 16; o > 0; o >>= 1)
        acc += __shfl_down_sync(0xffffffffu, acc, o);

    const int lane = t & 31, wid = t >> 5;
    if (lane == 0) s_part[wid] = acc;
    __syncthreads();

    if (wid == 0) {
        int nwarps = blockDim.x >> 5;
        float v = (lane < nwarps) ? s_part[lane] : 0.0f;
        #pragma unroll
        for (int o = 16; o > 0; o >>= 1)
            v += __shfl_down_sync(0xffffffffu, v, o);
        if (lane == 0)
            atomicAdd(&g_acc, (double)v);
    }
}

__global__ void bce_finalize_kernel(float* __restrict__ out, long long n_total) {
    out[0] = (float)(g_acc / (double)n_total);
}

extern "C" void kernel_launch(void* const* d_in, const int* in_sizes, int n_in,
                              void* d_out, int out_size) {
    const float* x = (const float*)d_in[0];
    const int*   l = (const int*)d_in[1];
    float* out = (float*)d_out;

    long long n = (long long)in_sizes[0];        // total elements (B*C)
    long long n_vec = n >> 2;                    // float4 vectors
    int rem = (int)(n & 3);
    long long tail_base = n_vec << 2;

    const int threads = 256;
    long long want = (n_vec + threads - 1) / threads;
    int blocks = (int)(want < 2368 ? (want > 0 ? want : 1) : 2368);

    bce_zero_kernel<<<1, 1>>>();
    bce_main_kernel<<<blocks, threads>>>(
        (const float4*)x, (const int4*)l, n_vec, rem,
        x + tail_base, l + tail_base, tail_base);
    bce_finalize_kernel<<<1, 1>>>(out, n);
}

// round 2
// speedup vs baseline: 1.1079x; 1.1079x over previous
#include <cuda_runtime.h>
#include <cuda_bf16.h>

// Per-channel class frequencies (compile-time constants from the reference).
__constant__ float c_W[23] = {
    0.0012597430655963838f, 0.0004919313290455535f, 0.0021106513104319356f,
    0.0007678117365508301f, 0.004719881670572202f,  0.000372272357115554f,
    0.029090425620315438f,  0.010056339432617042f,  0.0034817436971298467f,
    0.0003057951504877765f, 0.003995280118329428f,  8.808229878180519e-05f,
    0.012070598793438699f,  0.016788818533845208f,  0.0017832510677901316f,
    0.0008758371973209686f, 0.0005933090691529143f, 0.0031992155689617922f,
    0.003212511010287348f,  0.0016685778863572154f, 0.0009356666832859684f,
    0.0010985358395240233f, 0.00103372056306194f
};

#define NBLOCKS 1184
#define NTHREADS 256

// Scratch (no allocations allowed). Every slot of g_part is written every run,
// so no zeroing pass is needed. g_count self-wraps back to 0 via atomicInc.
__device__ float    g_part[NBLOCKS];
__device__ unsigned g_count = 0;

__global__ __launch_bounds__(NTHREADS, 8)
void bce_fused_kernel(const float4* __restrict__ x4,
                      const int4*   __restrict__ l4,
                      int n_vec, int rem,
                      const float* __restrict__ x_tail,
                      const int*   __restrict__ l_tail,
                      int tail_base,
                      float* __restrict__ out, float inv_n) {
    __shared__ float  s_w0[23];   // weight when label == 0  (= W+1)
    __shared__ float  s_w1[23];   // weight when label == 1  (= 1 + 1/W)
    __shared__ float  s_part[NTHREADS / 32];
    __shared__ double s_dpart[NTHREADS / 32];
    __shared__ bool   s_is_last;

    const int t = threadIdx.x;
    if (t < 23) {
        float w = c_W[t];
        s_w0[t] = w + 1.0f;
        s_w1[t] = 1.0f + __frcp_rn(w);
    }
    __syncthreads();

    const int stride = NBLOCKS * NTHREADS;
    const int gtid   = blockIdx.x * NTHREADS + t;

    // channel of first element of first vector; per-iteration advance constant
    int c_base = (int)((4ll * (long long)gtid) % 23);
    const int d = (int)((4ll * (long long)stride) % 23);

    float acc = 0.0f;
    for (int v = gtid; v < n_vec; v += stride) {
        float4 xv = __ldg(&x4[v]);
        int4   lv = __ldg(&l4[v]);

        int c = c_base;
        c_base += d; if (c_base >= 23) c_base -= 23;

        float xs[4] = { xv.x, xv.y, xv.z, xv.w };
        int   ls[4] = { lv.x, lv.y, lv.z, lv.w };
        #pragma unroll
        for (int j = 0; j < 4; ++j) {
            bool  pos = (ls[j] > 0);
            float arg = pos ? xs[j] : (1.0f - xs[j]);
            float w   = pos ? s_w1[c] : s_w0[c];
            acc = fmaf(w, -__logf(arg), acc);
            c = (c == 22) ? 0 : (c + 1);
        }
    }

    // scalar tail (n % 4 elements)
    if (gtid < rem) {
        int   i   = tail_base + gtid;
        int   lab = __ldg(&l_tail[gtid]);
        float xv  = __ldg(&x_tail[gtid]);
        int   c   = i % 23;
        bool  pos = (lab > 0);
        float arg = pos ? xv : (1.0f - xv);
        float w   = pos ? s_w1[c] : s_w0[c];
        acc = fmaf(w, -__logf(arg), acc);
    }

    // intra-block reduce (f32)
    #pragma unroll
    for (int o = 16; o > 0; o >>= 1)
        acc += __shfl_down_sync(0xffffffffu, acc, o);

    const int lane = t & 31, wid = t >> 5;
    if (lane == 0) s_part[wid] = acc;
    __syncthreads();

    if (t == 0) {
        float b = 0.0f;
        #pragma unroll
        for (int w = 0; w < NTHREADS / 32; ++w) b += s_part[w];
        g_part[blockIdx.x] = b;
        __threadfence();
        unsigned ticket = atomicInc(&g_count, NBLOCKS - 1); // wraps to 0
        s_is_last = (ticket == NBLOCKS - 1);
    }
    __syncthreads();

    // last block performs the final deterministic reduction in double
    if (s_is_last) {
        __threadfence();
        double dsum = 0.0;
        for (int i = t; i < NBLOCKS; i += NTHREADS)
            dsum += (double)g_part[i];
        #pragma unroll
        for (int o = 16; o > 0; o >>= 1)
            dsum += __shfl_down_sync(0xffffffffu, dsum, o);
        if (lane == 0) s_dpart[wid] = dsum;
        __syncthreads();
        if (t == 0) {
            double tot = 0.0;
            #pragma unroll
            for (int w = 0; w < NTHREADS / 32; ++w) tot += s_dpart[w];
            out[0] = (float)(tot * (double)inv_n);
        }
    }
}

extern "C" void kernel_launch(void* const* d_in, const int* in_sizes, int n_in,
                              void* d_out, int out_size) {
    const float* x = (const float*)d_in[0];
    const int*   l = (const int*)d_in[1];
    float* out = (float*)d_out;

    long long n = (long long)in_sizes[0];   // total elements (B*C) = 23e6
    int n_vec = (int)(n >> 2);
    int rem = (int)(n & 3);
    int tail_base = n_vec << 2;

    bce_fused_kernel<<<NBLOCKS, NTHREADS>>>(
        (const float4*)x, (const int4*)l, n_vec, rem,
        x + (long long)tail_base, l + (long long)tail_base, tail_base,
        out, 1.0f / (float)n);
}

// round 3
// speedup vs baseline: 1.1159x; 1.0072x over previous
#include <cuda_runtime.h>
#include <cuda_bf16.h>

// Per-channel class frequencies (compile-time constants from the reference).
__constant__ float c_W[23] = {
    0.0012597430655963838f, 0.0004919313290455535f, 0.0021106513104319356f,
    0.0007678117365508301f, 0.004719881670572202f,  0.000372272357115554f,
    0.029090425620315438f,  0.010056339432617042f,  0.0034817436971298467f,
    0.0003057951504877765f, 0.003995280118329428f,  8.808229878180519e-05f,
    0.012070598793438699f,  0.016788818533845208f,  0.0017832510677901316f,
    0.0008758371973209686f, 0.0005933090691529143f, 0.0031992155689617922f,
    0.003212511010287348f,  0.0016685778863572154f, 0.0009356666832859684f,
    0.0010985358395240233f, 0.00103372056306194f
};

// NB*NT must be ≡ 0 (mod 23) so each thread's channel pattern is loop-invariant.
// 1173 = 23*51 blocks, 256 threads -> 300288 threads, one wave (≤8 CTAs/SM).
#define NBLOCKS 1173
#define NTHREADS 256
#define LN2F 0.6931471805599453f

// Scratch (no allocations allowed). Every g_part slot is written every run;
// g_count self-wraps to 0 via atomicInc -> graph-replay safe.
__device__ float    g_part[NBLOCKS];
__device__ unsigned g_count = 0;

__global__ __launch_bounds__(NTHREADS, 8)
void bce_fused_kernel(const float4* __restrict__ x4,
                      const int4*   __restrict__ l4,
                      int n_vec, int rem,
                      const float* __restrict__ x_tail,
                      const int*   __restrict__ l_tail,
                      int tail_base,
                      float* __restrict__ out, float inv_n) {
    __shared__ float  s_w0[23];   // ln2 * (weight when label==0) = ln2*(W+1)
    __shared__ float  s_w1[23];   // ln2 * (weight when label==1) = ln2*(1+1/W)
    __shared__ float  s_part[NTHREADS / 32];
    __shared__ double s_dpart[NTHREADS / 32];
    __shared__ bool   s_is_last;

    const int t = threadIdx.x;
    if (t < 23) {
        float w = c_W[t];
        s_w0[t] = LN2F * (w + 1.0f);
        s_w1[t] = LN2F * (1.0f + __frcp_rn(w));
    }
    __syncthreads();

    const int stride = NBLOCKS * NTHREADS;        // 4*stride % 23 == 0
    const int gtid   = blockIdx.x * NTHREADS + t;

    // Fixed channels for this thread (invariant across loop iterations).
    int c0 = (int)((4ll * (long long)gtid) % 23);
    int c1 = c0 + 1; if (c1 >= 23) c1 -= 23;
    int c2 = c1 + 1; if (c2 >= 23) c2 -= 23;
    int c3 = c2 + 1; if (c3 >= 23) c3 -= 23;

    // Preload the 8 weights into registers — no LDS in the hot loop.
    const float w00 = s_w0[c0], w10 = s_w1[c0];
    const float w01 = s_w0[c1], w11 = s_w1[c1];
    const float w02 = s_w0[c2], w12 = s_w1[c2];
    const float w03 = s_w0[c3], w13 = s_w1[c3];

    float acc0 = 0.0f, acc1 = 0.0f;

    int v = gtid;
    // Unrolled x2: 4 LDG.128 in flight per iteration.
    for (; v + stride < n_vec; v += 2 * stride) {
        float4 xa = __ldcs(&x4[v]);
        int4   la = __ldcs(&l4[v]);
        float4 xb = __ldcs(&x4[v + stride]);
        int4   lb = __ldcs(&l4[v + stride]);

        {
            bool p0 = la.x > 0, p1 = la.y > 0, p2 = la.z > 0, p3 = la.w > 0;
            acc0 = fmaf(p0 ? w10 : w00, -__log2f(p0 ? xa.x : 1.0f - xa.x), acc0);
            acc0 = fmaf(p1 ? w11 : w01, -__log2f(p1 ? xa.y : 1.0f - xa.y), acc0);
            acc0 = fmaf(p2 ? w12 : w02, -__log2f(p2 ? xa.z : 1.0f - xa.z), acc0);
            acc0 = fmaf(p3 ? w13 : w03, -__log2f(p3 ? xa.w : 1.0f - xa.w), acc0);
        }
        {
            bool p0 = lb.x > 0, p1 = lb.y > 0, p2 = lb.z > 0, p3 = lb.w > 0;
            acc1 = fmaf(p0 ? w10 : w00, -__log2f(p0 ? xb.x : 1.0f - xb.x), acc1);
            acc1 = fmaf(p1 ? w11 : w01, -__log2f(p1 ? xb.y : 1.0f - xb.y), acc1);
            acc1 = fmaf(p2 ? w12 : w02, -__log2f(p2 ? xb.z : 1.0f - xb.z), acc1);
            acc1 = fmaf(p3 ? w13 : w03, -__log2f(p3 ? xb.w : 1.0f - xb.w), acc1);
        }
    }
    if (v < n_vec) {
        float4 xa = __ldcs(&x4[v]);
        int4   la = __ldcs(&l4[v]);
        bool p0 = la.x > 0, p1 = la.y > 0, p2 = la.z > 0, p3 = la.w > 0;
        acc0 = fmaf(p0 ? w10 : w00, -__log2f(p0 ? xa.x : 1.0f - xa.x), acc0);
        acc0 = fmaf(p1 ? w11 : w01, -__log2f(p1 ? xa.y : 1.0f - xa.y), acc0);
        acc0 = fmaf(p2 ? w12 : w02, -__log2f(p2 ? xa.z : 1.0f - xa.z), acc0);
        acc0 = fmaf(p3 ? w13 : w03, -__log2f(p3 ? xa.w : 1.0f - xa.w), acc0);
    }

    float acc = acc0 + acc1;

    // Scalar tail (n % 4 elements; 0 for B*C = 23e6 but kept for generality).
    if (gtid < rem) {
        int   i   = tail_base + gtid;
        int   lab = __ldg(&l_tail[gtid]);
        float xv  = __ldg(&x_tail[gtid]);
        int   c   = i % 23;
        bool  pos = (lab > 0);
        float arg = pos ? xv : (1.0f - xv);
        float w   = pos ? s_w1[c] : s_w0[c];
        acc = fmaf(w, -__log2f(arg), acc);
    }

    // Intra-block reduce (f32).
    #pragma unroll
    for (int o = 16; o > 0; o >>= 1)
        acc += __shfl_down_sync(0xffffffffu, acc, o);

    const int lane = t & 31, wid = t >> 5;
    if (lane == 0) s_part[wid] = acc;
    __syncthreads();

    if (t == 0) {
        float b = 0.0f;
        #pragma unroll
        for (int w = 0; w < NTHREADS / 32; ++w) b += s_part[w];
        g_part[blockIdx.x] = b;
        __threadfence();
        unsigned ticket = atomicInc(&g_count, NBLOCKS - 1); // wraps to 0
        s_is_last = (ticket == NBLOCKS - 1);
    }
    __syncthreads();

    // Last block: deterministic final reduction in double.
    if (s_is_last) {
        __threadfence();
        double dsum = 0.0;
        for (int i = t; i < NBLOCKS; i += NTHREADS)
            dsum += (double)g_part[i];
        #pragma unroll
        for (int o = 16; o > 0; o >>= 1)
            dsum += __shfl_down_sync(0xffffffffu, dsum, o);
        if (lane == 0) s_dpart[wid] = dsum;
        __syncthreads();
        if (t == 0) {
            double tot = 0.0;
            #pragma unroll
            for (int w = 0; w < NTHREADS / 32; ++w) tot += s_dpart[w];
            out[0] = (float)(tot * (double)inv_n);
        }
    }
}

extern "C" void kernel_launch(void* const* d_in, const int* in_sizes, int n_in,
                              void* d_out, int out_size) {
    const float* x = (const float*)d_in[0];
    const int*   l = (const int*)d_in[1];
    float* out = (float*)d_out;

    long long n = (long long)in_sizes[0];   // total elements (B*C) = 23e6
    int n_vec = (int)(n >> 2);
    int rem = (int)(n & 3);
    int tail_base = n_vec << 2;

    bce_fused_kernel<<<NBLOCKS, NTHREADS>>>(
        (const float4*)x, (const int4*)l, n_vec, rem,
        x + (long long)tail_base, l + (long long)tail_base, tail_base,
        out, 1.0f / (float)n);
}